// round 17
// baseline (speedup 1.0000x reference)
#include <cuda_runtime.h>
#include <cuda_bf16.h>
#include <cstdint>

#define N_NODES 100000
#define E_EDGES 1000000
#define H_DIM   64
#define OUT_DIM 16
#define R_REL   90
#define B_BAS   8
#define SC_EPB  2048
#define SB_BLKS ((E_EDGES + SC_EPB - 1) / SC_EPB)   // 489

typedef unsigned long long ull;

// ---------------- device scratch ----------------
__device__ uint32_t g_WT0[R_REL * H_DIM * H_DIM];  // packed (hi|lo<<16) bf16 of W^T: [r][o*64+i]
__device__ uint32_t g_WT1[R_REL * H_DIM * H_DIM];
__device__ float    g_W2[R_REL * H_DIM * OUT_DIM];
__device__ int      g_bh[SB_BLKS * R_REL];
__device__ int      g_off[R_REL + 1];
__device__ int      g_cur[R_REL];
__device__ int4     g_edges[E_EDGES];
__device__ float    g_h1[N_NODES * H_DIM];
__device__ float    g_h2[N_NODES * H_DIM];

#define W64_SZ (R_REL * H_DIM * H_DIM)
#define W16_SZ (R_REL * H_DIM * OUT_DIM)
#define H64Q   (N_NODES * H_DIM / 4)
#define H16Q   (N_NODES * OUT_DIM / 4)
#define FLAT_TOT (2 * H64Q + H16Q + 2 * W64_SZ + W16_SZ)

// ---------------- fused prep: hist + W precompute + bias init -------------
__global__ void __launch_bounds__(256) k_prep(
    const int* __restrict__ et,
    const float* __restrict__ c0, const float* __restrict__ b0,
    const float* __restrict__ c1, const float* __restrict__ b1,
    const float* __restrict__ c2, const float* __restrict__ b2,
    const float* __restrict__ bias0, const float* __restrict__ bias1,
    const float* __restrict__ bias2, float* __restrict__ out)
{
    int b = blockIdx.x;
    int t = threadIdx.x;
    if (b < SB_BLKS) {
        __shared__ int h[R_REL];
        for (int i = t; i < R_REL; i += 256) h[i] = 0;
        __syncthreads();
        int base = b * SC_EPB;
#pragma unroll
        for (int i = 0; i < 8; i++) {
            int e = base + i * 256 + t;
            if (e < E_EDGES) atomicAdd(&h[et[e]], 1);
        }
        __syncthreads();
        for (int i = t; i < R_REL; i += 256)
            g_bh[b * R_REL + i] = h[i];
        return;
    }
    int idx = (b - SB_BLKS) * 256 + t;
    if (idx < H64Q) {
        ((float4*)g_h1)[idx] = ((const float4*)bias0)[idx & 15];
    } else if (idx < 2 * H64Q) {
        int i = idx - H64Q;
        ((float4*)g_h2)[i] = ((const float4*)bias1)[i & 15];
    } else if (idx < 2 * H64Q + H16Q) {
        int i = idx - 2 * H64Q;
        ((float4*)out)[i] = ((const float4*)bias2)[i & 3];
    } else if (idx < FLAT_TOT) {
        int li = idx - (2 * H64Q + H16Q);
        if (li < 2 * W64_SZ) {
            const float* coeff = (li < W64_SZ) ? c0 : c1;
            const float* bases = (li < W64_SZ) ? b0 : b1;
            uint32_t* WT = (li < W64_SZ) ? g_WT0 : g_WT1;
            int lw = (li < W64_SZ) ? li : li - W64_SZ;
            int r  = lw / (H_DIM * H_DIM);
            int io = lw - r * (H_DIM * H_DIM);
            float s = 0.f;
#pragma unroll
            for (int bb = 0; bb < B_BAS; bb++)
                s = fmaf(coeff[r * B_BAS + bb], bases[bb * H_DIM * H_DIM + io], s);
            int i = io >> 6, o = io & 63;
            __nv_bfloat16 hi = __float2bfloat16(s);
            __nv_bfloat16 lo = __float2bfloat16(s - __bfloat162float(hi));
            uint32_t u = (uint32_t)__bfloat16_as_ushort(hi) |
                         ((uint32_t)__bfloat16_as_ushort(lo) << 16);
            WT[r * (H_DIM * H_DIM) + o * H_DIM + i] = u;
        } else {
            int lw = li - 2 * W64_SZ;
            int r  = lw / (H_DIM * OUT_DIM);
            int io = lw - r * (H_DIM * OUT_DIM);
            float s = 0.f;
#pragma unroll
            for (int bb = 0; bb < B_BAS; bb++)
                s = fmaf(c2[r * B_BAS + bb], b2[bb * H_DIM * OUT_DIM + io], s);
            g_W2[lw] = s;
        }
    }
}

// ---------------- scan ----------------
__global__ void __launch_bounds__(1024) k_scan2() {
    __shared__ int tot[R_REL];
    int t = threadIdx.x;
    if (t < R_REL) tot[t] = 0;
    __syncthreads();
    if (t < R_REL * 11) {
        int r = t / 11, k = t % 11;
        int s = 0;
        for (int b = k; b < SB_BLKS; b += 11) s += g_bh[b * R_REL + r];
        if (s) atomicAdd(&tot[r], s);
    }
    __syncthreads();
    if (t == 0) {
        int a = 0;
        for (int r = 0; r < R_REL; r++) {
            int c = tot[r]; tot[r] = a; a += c;
        }
        g_off[R_REL] = a;
    }
    __syncthreads();
    if (t < R_REL) {
        g_off[t] = tot[t];
        g_cur[t] = tot[t];
    }
}

__global__ void __launch_bounds__(256) k_scatter(const int* __restrict__ src,
                                                 const int* __restrict__ dst,
                                                 const int* __restrict__ et,
                                                 const float* __restrict__ norm) {
    __shared__ int scnt[R_REL];
    __shared__ int sbase[R_REL];
    int t = threadIdx.x;
    for (int i = t; i < R_REL; i += 256) scnt[i] = 0;
    __syncthreads();
    int base = blockIdx.x * SC_EPB;
    int r[8], rk[8];
#pragma unroll
    for (int i = 0; i < 8; i++) {
        int e = base + i * 256 + t;
        if (e < E_EDGES) {
            r[i]  = et[e];
            rk[i] = atomicAdd(&scnt[r[i]], 1);
        } else r[i] = -1;
    }
    __syncthreads();
    for (int i = t; i < R_REL; i += 256)
        sbase[i] = scnt[i] ? atomicAdd(&g_cur[i], scnt[i]) : 0;
    __syncthreads();
#pragma unroll
    for (int i = 0; i < 8; i++) {
        int e = base + i * 256 + t;
        if (r[i] >= 0) {
            int p = sbase[r[i]] + rk[i];
            g_edges[p] = make_int4(src[e], dst[e], r[i], __float_as_int(norm[e]));
        }
    }
}

// ---------------- helpers ----------------
__device__ __forceinline__ uint32_t smem_u32(const void* p) {
    uint32_t a;
    asm("{ .reg .u64 t; cvta.to.shared.u64 t, %1; cvt.u32.u64 %0, t; }" : "=r"(a) : "l"(p));
    return a;
}

#define LDSM4(r0, r1, r2, r3, a) \
    asm volatile("ldmatrix.sync.aligned.m8n8.x4.shared.b16 {%0,%1,%2,%3}, [%4];" \
        : "=r"(r0), "=r"(r1), "=r"(r2), "=r"(r3) : "r"(a))

#define MMA16816(c, a0, a1, a2, a3, b0, b1) \
    asm volatile("mma.sync.aligned.m16n8k16.row.col.f32.bf16.bf16.f32 " \
        "{%0,%1,%2,%3}, {%4,%5,%6,%7}, {%8,%9}, {%0,%1,%2,%3};" \
        : "+f"((c)[0]), "+f"((c)[1]), "+f"((c)[2]), "+f"((c)[3]) \
        : "r"(a0), "r"(a1), "r"(a2), "r"(a3), "r"(b0), "r"(b1))

// ---------------- HMMA edge kernel, H->H -----------------------------------
// CTA = 256 edges. xs[256][192] bf16 split rows (A' = [hi|lo|hi], norm+relu
// folded, fp32-exact before split); ws[64][192] (B' = [hi|hi|lo]) staged per
// relation segment. Warp = 32 edges = 2 m16 tiles sharing B fragments.
// K=192 = 12 k-steps of m16n8k16 bf16 HMMA; masked red.v2 epilogue.
#define TILE    256
#define XSTR    400                         // row stride bytes (16B-aligned, conflict-free)
#define WS_OFF  (TILE * XSTR)               // 102400
#define SMEM_HM (WS_OFF + 64 * XSTR)        // 128000

template<bool RELU>
__global__ void __launch_bounds__(256, 1) k_hmma64(const float* __restrict__ x,
                                                   const uint32_t* __restrict__ WT,
                                                   float* __restrict__ h) {
    extern __shared__ char sm[];
    const uint32_t smb = smem_u32(sm);
    const int tid  = threadIdx.x;
    const int warp = tid >> 5;
    const int lane = tid & 31;

    int tile = blockIdx.x * TILE;
    int lim  = min(tile + TILE, E_EDGES);

    // ---- stage A: one thread per edge row ----
    {
        int e = min(tile + tid, E_EDGES - 1);
        int4 em = g_edges[e];
        float nrm = __int_as_float(em.w);
        const float4* xr = (const float4*)(x + em.x * H_DIM);
        char* ar = sm + tid * XSTR;
#pragma unroll
        for (int j = 0; j < 16; j++) {
            float4 v = xr[j];
            if (RELU) {
                v.x = fmaxf(v.x, 0.f); v.y = fmaxf(v.y, 0.f);
                v.z = fmaxf(v.z, 0.f); v.w = fmaxf(v.w, 0.f);
            }
            v.x *= nrm; v.y *= nrm; v.z *= nrm; v.w *= nrm;
            float f[4] = {v.x, v.y, v.z, v.w};
            uint32_t uh[2], ul[2];
#pragma unroll
            for (int q = 0; q < 2; q++) {
                __nv_bfloat16 h0 = __float2bfloat16(f[2 * q]);
                __nv_bfloat16 h1 = __float2bfloat16(f[2 * q + 1]);
                __nv_bfloat16 l0 = __float2bfloat16(f[2 * q] - __bfloat162float(h0));
                __nv_bfloat16 l1 = __float2bfloat16(f[2 * q + 1] - __bfloat162float(h1));
                uh[q] = (uint32_t)__bfloat16_as_ushort(h0) |
                        ((uint32_t)__bfloat16_as_ushort(h1) << 16);
                ul[q] = (uint32_t)__bfloat16_as_ushort(l0) |
                        ((uint32_t)__bfloat16_as_ushort(l1) << 16);
            }
            ull UH = uh[0] | ((ull)uh[1] << 32);
            ull UL = ul[0] | ((ull)ul[1] << 32);
            int k = 4 * j;
            *(ull*)(ar + k * 2)         = UH;   // hi block
            *(ull*)(ar + (128 + k) * 2) = UH;   // hi dup
            *(ull*)(ar + (64 + k) * 2)  = UL;   // lo block
        }
    }

    int pos = tile;
    while (pos < lim) {
        int r      = ((const int*)g_edges)[pos * 4 + 2];
        int segEnd = min(lim, g_off[r + 1]);

        __syncthreads();   // A staged / prior segment's ldmatrix reads done
        // ---- stage B: W_r^T split [hi|hi|lo], 4 threads per output row ----
        {
            int o = tid >> 2, i0 = (tid & 3) * 16;
            const uint4* wt = (const uint4*)(WT + r * (H_DIM * H_DIM) + o * H_DIM + i0);
            char* wr = sm + WS_OFF + o * XSTR;
#pragma unroll
            for (int q = 0; q < 4; q++) {
                uint4 u = wt[q];
                uint32_t uh0 = (u.x & 0xffffu) | (u.y << 16);
                uint32_t ul0 = (u.x >> 16) | (u.y & 0xffff0000u);
                uint32_t uh1 = (u.z & 0xffffu) | (u.w << 16);
                uint32_t ul1 = (u.z >> 16) | (u.w & 0xffff0000u);
                ull UH = uh0 | ((ull)uh1 << 32);
                ull UL = ul0 | ((ull)ul1 << 32);
                int k = i0 + 4 * q;
                *(ull*)(wr + k * 2)         = UH;
                *(ull*)(wr + (64 + k) * 2)  = UH;
                *(ull*)(wr + (128 + k) * 2) = UL;
            }
        }
        __syncthreads();

        int wb = tile + warp * 32;
        if (wb < segEnd && wb + 32 > pos) {
            float acc[64];
#pragma unroll
            for (int i = 0; i < 64; i++) acc[i] = 0.f;

            uint32_t arow0 = smb + (warp * 32 + (lane & 15)) * XSTR + ((lane >> 4) << 4);
            uint32_t arow1 = arow0 + 16 * XSTR;
            uint32_t brow  = smb + WS_OFF +
                             (((lane >> 4) & 1) * 8 + (lane & 7)) * XSTR +
                             (((lane >> 3) & 1) << 4);
#pragma unroll
            for (int ks = 0; ks < 12; ks++) {
                uint32_t A0[4], A1[4];
                LDSM4(A0[0], A0[1], A0[2], A0[3], arow0 + ks * 32);
                LDSM4(A1[0], A1[1], A1[2], A1[3], arow1 + ks * 32);
#pragma unroll
                for (int p = 0; p < 4; p++) {
                    uint32_t b0, b1, b2, b3;
                    LDSM4(b0, b1, b2, b3, brow + p * 16 * XSTR + ks * 32);
                    MMA16816(acc + 16 * p + 0,  A0[0], A0[1], A0[2], A0[3], b0, b1);
                    MMA16816(acc + 16 * p + 4,  A0[0], A0[1], A0[2], A0[3], b2, b3);
                    MMA16816(acc + 16 * p + 8,  A1[0], A1[1], A1[2], A1[3], b0, b1);
                    MMA16816(acc + 16 * p + 12, A1[0], A1[1], A1[2], A1[3], b2, b3);
                }
            }

            // ---- epilogue: D thread (g,t): rows g/g+8, cols 2t/2t+1 ----
            int g = lane >> 2, t4 = lane & 3;
#pragma unroll
            for (int mt = 0; mt < 2; mt++) {
                int e0 = wb + mt * 16 + g;
                int e1 = e0 + 8;
                bool v0 = (e0 >= pos) && (e0 < segEnd);
                bool v1 = (e1 >= pos) && (e1 < segEnd);
                int d0 = g_edges[min(e0, E_EDGES - 1)].y;
                int d1 = g_edges[min(e1, E_EDGES - 1)].y;
                float* h0p = h + d0 * H_DIM + 2 * t4;
                float* h1p = h + d1 * H_DIM + 2 * t4;
#pragma unroll
                for (int p = 0; p < 4; p++) {
#pragma unroll
                    for (int w = 0; w < 2; w++) {
                        int base = 16 * p + 8 * mt + 4 * w;
                        int coff = (2 * p + w) * 8;
                        if (v0)
                            asm volatile("red.global.add.v2.f32 [%0], {%1, %2};"
                                         :: "l"(h0p + coff), "f"(acc[base]),
                                            "f"(acc[base + 1]) : "memory");
                        if (v1)
                            asm volatile("red.global.add.v2.f32 [%0], {%1, %2};"
                                         :: "l"(h1p + coff), "f"(acc[base + 2]),
                                            "f"(acc[base + 3]) : "memory");
                    }
                }
            }
        }
        pos = segEnd;
    }
}

// ---------------- f32x2 helpers (edge16) ----------------
#define FMA2(acc, a, b) \
    asm("fma.rn.f32x2 %0, %1, %2, %0;" : "+l"(acc) : "l"(a), "l"(b))
#define MUL2(acc, b) \
    asm("mul.rn.f32x2 %0, %0, %1;" : "+l"(acc) : "l"(b))
#define DUP2(d, s) \
    asm("mov.b64 %0, {%1, %1};" : "=l"(d) : "r"(__float_as_uint(s)))
#define UNPK2(f0, f1, s) \
    asm("mov.b64 {%0, %1}, %2;" : "=f"(f0), "=f"(f1) : "l"(s))

// ---------------- edge kernel, H->OUT: 2 edges/thread, relu fused ----------
__global__ void __launch_bounds__(256, 4) k_edge16(const float* __restrict__ x,
                                                   const float* __restrict__ W,
                                                   float* __restrict__ h) {
    __shared__ float Ws[H_DIM * OUT_DIM];
    const int tid  = threadIdx.x;
    int base = blockIdx.x * 512;
    int lim  = min(base + 512, E_EDGES);

    int e0 = base + tid * 2;
    int e1 = e0 + 1;
    int4 ed0 = g_edges[min(e0, lim - 1)];
    int4 ed1 = g_edges[min(e1, lim - 1)];
    const float* x0 = x + ed0.x * H_DIM;
    const float* x1 = x + ed1.x * H_DIM;

    int pos = base;
    while (pos < lim) {
        int r      = ((const int*)g_edges)[pos * 4 + 2];
        int segEnd = min(lim, g_off[r + 1]);
        __syncthreads();
        ((float4*)Ws)[tid] = ((const float4*)(W + r * (H_DIM * OUT_DIM)))[tid];
        __syncthreads();

        if (e0 < segEnd && e1 >= pos && e0 < lim) {
            ull acc[16];
#pragma unroll
            for (int j = 0; j < 16; j++) acc[j] = 0ull;

            for (int ic = 0; ic < 8; ic++) {
                float4 a0 = *(const float4*)(x0 + ic * 8);
                float4 a1 = *(const float4*)(x0 + ic * 8 + 4);
                float4 b0 = *(const float4*)(x1 + ic * 8);
                float4 b1 = *(const float4*)(x1 + ic * 8 + 4);
#pragma unroll
                for (int i = 0; i < 8; i++) {
                    const float* Wrow = Ws + (ic * 8 + i) * OUT_DIM;
                    ulonglong2 wA = *(const ulonglong2*)(Wrow);
                    ulonglong2 wB = *(const ulonglong2*)(Wrow + 4);
                    ulonglong2 wC = *(const ulonglong2*)(Wrow + 8);
                    ulonglong2 wD = *(const ulonglong2*)(Wrow + 12);
                    float xi0 = (i < 4) ? ((const float*)&a0)[i] : ((const float*)&a1)[i - 4];
                    float xi1 = (i < 4) ? ((const float*)&b0)[i] : ((const float*)&b1)[i - 4];
                    ull A0, A1;
                    DUP2(A0, fmaxf(xi0, 0.f));
                    DUP2(A1, fmaxf(xi1, 0.f));
                    FMA2(acc[0], A0, wA.x); FMA2(acc[1], A0, wA.y);
                    FMA2(acc[2], A0, wB.x); FMA2(acc[3], A0, wB.y);
                    FMA2(acc[4], A0, wC.x); FMA2(acc[5], A0, wC.y);
                    FMA2(acc[6], A0, wD.x); FMA2(acc[7], A0, wD.y);
                    FMA2(acc[8],  A1, wA.x); FMA2(acc[9],  A1, wA.y);
                    FMA2(acc[10], A1, wB.x); FMA2(acc[11], A1, wB.y);
                    FMA2(acc[12], A1, wC.x); FMA2(acc[13], A1, wC.y);
                    FMA2(acc[14], A1, wD.x); FMA2(acc[15], A1, wD.y);
                }
            }

            if (e0 >= pos && e0 < segEnd) {
                ull N0; DUP2(N0, __int_as_float(ed0.w));
                float* hp = h + ed0.y * OUT_DIM;
#pragma unroll
                for (int q = 0; q < 4; q++) {
                    MUL2(acc[2 * q], N0); MUL2(acc[2 * q + 1], N0);
                    float f0, f1, f2, f3;
                    UNPK2(f0, f1, acc[2 * q]);
                    UNPK2(f2, f3, acc[2 * q + 1]);
                    asm volatile("red.global.add.v4.f32 [%0], {%1, %2, %3, %4};"
                                 :: "l"(hp + q * 4), "f"(f0), "f"(f1), "f"(f2), "f"(f3)
                                 : "memory");
                }
            }
            if (e1 >= pos && e1 < segEnd) {
                ull N1; DUP2(N1, __int_as_float(ed1.w));
                float* hp = h + ed1.y * OUT_DIM;
#pragma unroll
                for (int q = 0; q < 4; q++) {
                    MUL2(acc[8 + 2 * q], N1); MUL2(acc[8 + 2 * q + 1], N1);
                    float f0, f1, f2, f3;
                    UNPK2(f0, f1, acc[8 + 2 * q]);
                    UNPK2(f2, f3, acc[8 + 2 * q + 1]);
                    asm volatile("red.global.add.v4.f32 [%0], {%1, %2, %3, %4};"
                                 :: "l"(hp + q * 4), "f"(f0), "f"(f1), "f"(f2), "f"(f3)
                                 : "memory");
                }
            }
        }
        pos = segEnd;
    }
}

// ---------------- launch ----------------
extern "C" void kernel_launch(void* const* d_in, const int* in_sizes, int n_in,
                              void* d_out, int out_size) {
    const float* feats  = (const float*)d_in[0];
    const float* coeff0 = (const float*)d_in[1];
    const float* bases0 = (const float*)d_in[2];
    const float* bias0  = (const float*)d_in[3];
    const float* coeff1 = (const float*)d_in[4];
    const float* bases1 = (const float*)d_in[5];
    const float* bias1  = (const float*)d_in[6];
    const float* coeff2 = (const float*)d_in[7];
    const float* bases2 = (const float*)d_in[8];
    const float* bias2  = (const float*)d_in[9];
    const int*   src    = (const int*)d_in[10];
    const int*   dst    = (const int*)d_in[11];
    const int*   etype  = (const int*)d_in[12];
    const float* norm   = (const float*)d_in[13];
    float*       out    = (float*)d_out;

    const int EBM  = (E_EDGES + TILE - 1) / TILE;   // 3907
    const int EB16 = (E_EDGES + 511) / 512;
    const int PREP_BLKS = SB_BLKS + (FLAT_TOT + 255) / 256;

    float *h1, *h2, *W2;
    uint32_t *WT0, *WT1;
    cudaGetSymbolAddress((void**)&h1,  g_h1);
    cudaGetSymbolAddress((void**)&h2,  g_h2);
    cudaGetSymbolAddress((void**)&WT0, g_WT0);
    cudaGetSymbolAddress((void**)&WT1, g_WT1);
    cudaGetSymbolAddress((void**)&W2,  g_W2);

    cudaFuncSetAttribute(k_hmma64<false>,
                         cudaFuncAttributeMaxDynamicSharedMemorySize, SMEM_HM);
    cudaFuncSetAttribute(k_hmma64<true>,
                         cudaFuncAttributeMaxDynamicSharedMemorySize, SMEM_HM);

    k_prep<<<PREP_BLKS, 256>>>(etype, coeff0, bases0, coeff1, bases1,
                               coeff2, bases2, bias0, bias1, bias2, out);
    k_scan2<<<1, 1024>>>();
    k_scatter<<<SB_BLKS, 256>>>(src, dst, etype, norm);
    // 4th launch -> ncu window
    k_hmma64<false><<<EBM, 256, SMEM_HM>>>(feats, WT0, h1);
    k_hmma64<true><<<EBM, 256, SMEM_HM>>>(h1, WT1, h2);
    k_edge16<<<EB16, 256>>>(h2, W2, out);
}